// round 4
// baseline (speedup 1.0000x reference)
#include <cuda_runtime.h>
#include <cstdint>

#define T_STEPS 1000
#define BATCH   2048
#define FEAT    40
#define H1      8
#define H2      6
#define G1      32
#define G2      24
#define NPAIR   1024

#define CT      10                    // timesteps per staged x-chunk
#define NCHUNK  (T_STEPS / CT)        // 100
#define F4ROW   (FEAT / 4)            // 10 float4 per (row, t)
#define SITES   (2 * CT * F4ROW)      // 200 float4 sites per chunk
#define NITER   ((SITES + 31) / 32)   // 7

typedef unsigned long long u64;

// ---------------- f32x2 helpers ----------------
__device__ __forceinline__ u64 pack2(float x, float y) {
    u64 r; asm("mov.b64 %0, {%1, %2};" : "=l"(r) : "f"(x), "f"(y)); return r;
}
__device__ __forceinline__ void unpack2(u64 v, float& x, float& y) {
    asm("mov.b64 {%0, %1}, %2;" : "=f"(x), "=f"(y) : "l"(v));
}
__device__ __forceinline__ u64 fma2(u64 a, u64 b, u64 c) {
    u64 d; asm("fma.rn.f32x2 %0, %1, %2, %3;" : "=l"(d) : "l"(a), "l"(b), "l"(c)); return d;
}
__device__ __forceinline__ u64 mul2(u64 a, u64 b) {
    u64 d; asm("mul.rn.f32x2 %0, %1, %2;" : "=l"(d) : "l"(a), "l"(b)); return d;
}
__device__ __forceinline__ u64 add2(u64 a, u64 b) {
    u64 d; asm("add.rn.f32x2 %0, %1, %2;" : "=l"(d) : "l"(a), "l"(b)); return d;
}
__device__ __forceinline__ u64 scale2(u64 v, float s) {
    float a, b; unpack2(v, a, b); return pack2(a * s, b * s);
}

// ---------------- activations: 1 MUFU each; input scale folded into weights
__device__ __forceinline__ float tanha(float x) {
    float r; asm("tanh.approx.f32 %0, %1;" : "=f"(r) : "f"(x)); return r;
}
// act(g_scaled) = ca + cn * tanh(g_scaled)   (g already has cm folded in)
__device__ __forceinline__ float actp(float g, float cn, float ca) {
    return fmaf(cn, tanha(g), ca);
}

__device__ __forceinline__ float shflf(float v, int src) {
    return __shfl_sync(0xffffffffu, v, src);
}

// input-projection partial: dot(x_row[t], cm*W_ih1[lane]) via pairwise f32x2
__device__ __forceinline__ float xdot(const u64* __restrict__ xr, int tc,
                                      const u64* __restrict__ w2) {
    const ulonglong2* q = reinterpret_cast<const ulonglong2*>(xr + tc * (FEAT / 2));
    ulonglong2 v = q[0];
    u64 a = mul2(w2[0], v.x);
    u64 d = mul2(w2[1], v.y);
#pragma unroll
    for (int p = 1; p < F4ROW; p++) {
        v = q[p];
        a = fma2(w2[2 * p],     v.x, a);
        d = fma2(w2[2 * p + 1], v.y, d);
    }
    a = add2(a, d);
    float ax, ay; unpack2(a, ax, ay);
    return ax + ay;
}

// ============================================================================
// one fused LSTM step: layer1(i) + layer2(i-1)
// slab layout (u64[24]): [2j]=h1[j], [2j+1]=x2[j] (j<8); [16+j]=h2[j] (j<6)
// ============================================================================
template <int RD>
__device__ __forceinline__ void lstm_step(
    float en, int tc, int lane,
    const u64* __restrict__ xr0, const u64* __restrict__ xr1,
    u64 (*shs)[24],
    const u64* w2, const u64* w1, const u64* wi2, const u64* wh2,
    u64 bias1, u64 bias2,
    float cn1, float ca1, float cn2, float ca2,
    float& c1x, float& c1y, float& c2x, float& c2y)
{
    constexpr int WR = RD ^ 1;

    // ---- input projection for this lane's gate (off the serial chain) ----
    float gin_x = xdot(xr0, tc, w2);
    float gin_y = xdot(xr1, tc, w2);
    u64 g1in = pack2(gin_x, gin_y);

    // ---- fused hidden MACs: 11 LDS.128, each feeding both layers ----
    const ulonglong2* hp = reinterpret_cast<const ulonglong2*>(&shs[RD][0]);
    ulonglong2 v0 = hp[0], v1 = hp[1], v2 = hp[2], v3 = hp[3];
    ulonglong2 v4 = hp[4], v5 = hp[5], v6 = hp[6], v7 = hp[7];
    ulonglong2 u0 = hp[8], u1 = hp[9], u2 = hp[10];

    u64 A = fma2(v0.x, w1[0], bias1);
    u64 B = mul2(v1.x, w1[1]);
    A = fma2(v2.x, w1[2], A);
    B = fma2(v3.x, w1[3], B);
    A = fma2(v4.x, w1[4], A);
    B = fma2(v5.x, w1[5], B);
    A = fma2(v6.x, w1[6], A);
    B = fma2(v7.x, w1[7], B);
    u64 g1 = add2(add2(A, B), g1in);

    u64 P = fma2(v0.y, wi2[0], bias2);
    u64 Q = mul2(v1.y, wi2[1]);
    u64 R = mul2(v2.y, wi2[2]);
    P = fma2(v3.y, wi2[3], P);
    Q = fma2(v4.y, wi2[4], Q);
    R = fma2(v5.y, wi2[5], R);
    P = fma2(v6.y, wi2[6], P);
    Q = fma2(v7.y, wi2[7], Q);
    R = fma2(u0.x, wh2[0], R);
    P = fma2(u0.y, wh2[1], P);
    Q = fma2(u1.x, wh2[2], Q);
    R = fma2(u1.y, wh2[3], R);
    P = fma2(u2.x, wh2[4], P);
    Q = fma2(u2.y, wh2[5], Q);
    u64 g2 = add2(add2(P, Q), R);

    // ---- activations (inputs pre-scaled; 1 MUFU + 1 fma each) ----
    float g1x, g1y; unpack2(g1, g1x, g1y);
    float g2x, g2y; unpack2(g2, g2x, g2y);
    float a1x = actp(g1x, cn1, ca1);
    float a1y = actp(g1y, cn1, ca1);
    float a2x = actp(g2x, cn2, ca2);
    float a2y = actp(g2y, cn2, ca2);

    // ---- gate gathers ----
    float f1x = shflf(a1x, lane + 8),  f1y = shflf(a1y, lane + 8);
    float i1x = shflf(a1x, lane + 16), i1y = shflf(a1y, lane + 16);
    float o1x = shflf(a1x, lane + 24), o1y = shflf(a1y, lane + 24);
    float f2x = shflf(a2x, lane + 6),  f2y = shflf(a2y, lane + 6);
    float i2x = shflf(a2x, lane + 12), i2y = shflf(a2y, lane + 12);
    float o2x = shflf(a2x, lane + 18), o2y = shflf(a2y, lane + 18);

    // ---- layer1 state (valid lanes 0..7) ----
    c1x = fmaf(f1x, c1x, a1x * i1x);
    c1y = fmaf(f1y, c1y, a1y * i1y);
    float h1x = o1x * tanha(c1x);
    float h1y = o1y * tanha(c1y);
    float x2x = tanha(h1x);
    float x2y = tanha(h1y);

    // ---- layer2 state (valid lanes 0..5) ----
    c2x = en * fmaf(f2x, c2x, a2x * i2x);
    c2y = en * fmaf(f2y, c2y, a2y * i2y);
    float h2x = o2x * tanha(c2x);
    float h2y = o2y * tanha(c2y);

    if (lane < H1) {
        ulonglong2 wv;
        wv.x = pack2(h1x, h1y);
        wv.y = pack2(x2x, x2y);
        *reinterpret_cast<ulonglong2*>(&shs[WR][2 * lane]) = wv;   // STS.128
    }
    if (lane < H2) shs[WR][16 + lane] = pack2(h2x, h2y);
    __syncwarp();
}

// ============================================================================
// fused kernel: 1 warp per batch pair
// ============================================================================
__global__ void __launch_bounds__(32)
fused_kernel(const float* __restrict__ x,
             const float* __restrict__ W_ih1,
             const float* __restrict__ W_hh1,
             const float* __restrict__ b_ih1,
             const float* __restrict__ b_hh1,
             const float* __restrict__ W_ih2,
             const float* __restrict__ W_hh2,
             const float* __restrict__ b_ih2,
             const float* __restrict__ b_hh2,
             const float* __restrict__ W_fc,
             const float* __restrict__ b_fc,
             float* __restrict__ out) {
    __shared__ __align__(16) u64 shs[2][24];
    __shared__ __align__(16) u64 sx[2][2][CT][FEAT / 2];  // [buf][row][t][fpairs]

    int lane = threadIdx.x;
    int w    = blockIdx.x;

    // activation constants; cm (input scale) is folded into weights below
    bool t1 = ((lane >> 3) == 2);
    float cm1 = t1 ? 1.f : 0.5f, cn1 = t1 ? 1.f : 0.5f, ca1 = t1 ? 0.f : 0.5f;
    bool t2 = (lane >= 12 && lane < 18);
    float cm2 = t2 ? 1.f : 0.5f, cn2 = t2 ? 1.f : 0.5f, ca2 = t2 ? 0.f : 0.5f;

    // ---- per-lane weights (scaled by cm) ----
    u64 w2[FEAT / 2];   // pairwise feature-packed proj weights
    {
        const u64* wrow = reinterpret_cast<const u64*>(W_ih1 + lane * FEAT);
#pragma unroll
        for (int p = 0; p < FEAT / 2; p++) w2[p] = scale2(wrow[p], cm1);
    }
    u64 w1[H1];
#pragma unroll
    for (int j = 0; j < H1; j++) {
        float v = cm1 * W_hh1[lane * H1 + j];
        w1[j] = pack2(v, v);
    }
    u64 wi2[H1], wh2[H2], bias2 = 0ull;
#pragma unroll
    for (int j = 0; j < H1; j++) wi2[j] = 0ull;
#pragma unroll
    for (int j = 0; j < H2; j++) wh2[j] = 0ull;
    if (lane < G2) {
#pragma unroll
        for (int j = 0; j < H1; j++) { float v = cm2 * W_ih2[lane * H1 + j]; wi2[j] = pack2(v, v); }
#pragma unroll
        for (int j = 0; j < H2; j++) { float v = cm2 * W_hh2[lane * H2 + j]; wh2[j] = pack2(v, v); }
        float bb = cm2 * (b_ih2[lane] + b_hh2[lane]);
        bias2 = pack2(bb, bb);
    }
    float b1s = cm1 * (b_ih1[lane] + b_hh1[lane]);
    u64 bias1 = pack2(b1s, b1s);

    if (lane < 24) shs[1][lane] = 0ull;   // zero state read by step 0

    // ---- x chunk staging pointers ----
    const float4* xb0 = reinterpret_cast<const float4*>(x + (size_t)(2 * w)     * T_STEPS * FEAT);
    const float4* xb1 = reinterpret_cast<const float4*>(x + (size_t)(2 * w + 1) * T_STEPS * FEAT);

    // preload chunk 0 into buffer 0
    {
        float4 f4[NITER];
#pragma unroll
        for (int i = 0; i < NITER; i++) {
            int s = lane + 32 * i;
            if (s < SITES) f4[i] = (s < SITES / 2) ? xb0[s] : xb1[s - SITES / 2];
        }
        float4* sb = reinterpret_cast<float4*>(&sx[0][0][0][0]);
#pragma unroll
        for (int i = 0; i < NITER; i++) {
            int s = lane + 32 * i;
            if (s < SITES) sb[s] = f4[i];
        }
    }
    __syncwarp();

    float c1x = 0.f, c1y = 0.f, c2x = 0.f, c2y = 0.f;

#pragma unroll 1
    for (int c = 0; c < NCHUNK; c++) {
        int b = c & 1;
        const u64* xr0 = &sx[b][0][0][0];
        const u64* xr1 = &sx[b][1][0][0];

        // issue prefetch LDGs for chunk c+1 (clamped on last chunk)
        int cn = (c + 1 < NCHUNK) ? c + 1 : c;
        const float4* p0 = xb0 + cn * (CT * F4ROW);
        const float4* p1 = xb1 + cn * (CT * F4ROW);
        float4 f4[NITER];
#pragma unroll
        for (int i = 0; i < NITER; i++) {
            int s = lane + 32 * i;
            if (s < SITES) f4[i] = (s < SITES / 2) ? p0[s] : p1[s - SITES / 2];
        }

        float en0 = (c == 0) ? 0.f : 1.f;
        lstm_step<1>(en0, 0, lane, xr0, xr1, shs, w2, w1, wi2, wh2, bias1, bias2,
                     cn1, ca1, cn2, ca2, c1x, c1y, c2x, c2y);
        lstm_step<0>(1.f, 1, lane, xr0, xr1, shs, w2, w1, wi2, wh2, bias1, bias2,
                     cn1, ca1, cn2, ca2, c1x, c1y, c2x, c2y);
        lstm_step<1>(1.f, 2, lane, xr0, xr1, shs, w2, w1, wi2, wh2, bias1, bias2,
                     cn1, ca1, cn2, ca2, c1x, c1y, c2x, c2y);
        lstm_step<0>(1.f, 3, lane, xr0, xr1, shs, w2, w1, wi2, wh2, bias1, bias2,
                     cn1, ca1, cn2, ca2, c1x, c1y, c2x, c2y);

        // stash prefetched chunk into the other buffer
        {
            float4* sb = reinterpret_cast<float4*>(&sx[b ^ 1][0][0][0]);
#pragma unroll
            for (int i = 0; i < NITER; i++) {
                int s = lane + 32 * i;
                if (s < SITES) sb[s] = f4[i];
            }
        }

#pragma unroll 3
        for (int k = 2; k < 5; k++) {
            lstm_step<1>(1.f, 2 * k,     lane, xr0, xr1, shs, w2, w1, wi2, wh2, bias1, bias2,
                         cn1, ca1, cn2, ca2, c1x, c1y, c2x, c2y);
            lstm_step<0>(1.f, 2 * k + 1, lane, xr0, xr1, shs, w2, w1, wi2, wh2, bias1, bias2,
                         cn1, ca1, cn2, ca2, c1x, c1y, c2x, c2y);
        }
    }

    // ---- epilogue: layer2(999) from slab[1]: x2(999) odd slots, h2(998) ----
    {
        const ulonglong2* hp = reinterpret_cast<const ulonglong2*>(&shs[1][0]);
        ulonglong2 v0 = hp[0], v1 = hp[1], v2 = hp[2], v3 = hp[3];
        ulonglong2 v4 = hp[4], v5 = hp[5], v6 = hp[6], v7 = hp[7];
        ulonglong2 u0 = hp[8], u1 = hp[9], u2 = hp[10];

        u64 P = fma2(v0.y, wi2[0], bias2);
        u64 Q = mul2(v1.y, wi2[1]);
        u64 R = mul2(v2.y, wi2[2]);
        P = fma2(v3.y, wi2[3], P);
        Q = fma2(v4.y, wi2[4], Q);
        R = fma2(v5.y, wi2[5], R);
        P = fma2(v6.y, wi2[6], P);
        Q = fma2(v7.y, wi2[7], Q);
        R = fma2(u0.x, wh2[0], R);
        P = fma2(u0.y, wh2[1], P);
        Q = fma2(u1.x, wh2[2], Q);
        R = fma2(u1.y, wh2[3], R);
        P = fma2(u2.x, wh2[4], P);
        Q = fma2(u2.y, wh2[5], Q);
        u64 g2 = add2(add2(P, Q), R);

        float g2x, g2y; unpack2(g2, g2x, g2y);
        float a2x = actp(g2x, cn2, ca2);
        float a2y = actp(g2y, cn2, ca2);
        float f2x = shflf(a2x, lane + 6),  f2y = shflf(a2y, lane + 6);
        float i2x = shflf(a2x, lane + 12), i2y = shflf(a2y, lane + 12);
        float o2x = shflf(a2x, lane + 18), o2y = shflf(a2y, lane + 18);
        c2x = fmaf(f2x, c2x, a2x * i2x);
        c2y = fmaf(f2y, c2y, a2y * i2y);
        float tx = tanha(o2x * tanha(c2x));   // tanh(h2(999))
        float ty = tanha(o2y * tanha(c2y));

        // FC + sigmoid
        float bf = b_fc[0];
        float sx_ = bf, sy_ = bf;
#pragma unroll
        for (int j = 0; j < H2; j++) {
            float vx = shflf(tx, j);
            float vy = shflf(ty, j);
            float wf = W_fc[j];
            sx_ = fmaf(vx, wf, sx_);
            sy_ = fmaf(vy, wf, sy_);
        }
        if (lane == 0) {
            out[2 * w]     = fmaf(0.5f, tanha(0.5f * sx_), 0.5f);
            out[2 * w + 1] = fmaf(0.5f, tanha(0.5f * sy_), 0.5f);
        }
    }
}

// ============================================================================
extern "C" void kernel_launch(void* const* d_in, const int* in_sizes, int n_in,
                              void* d_out, int out_size) {
    const float* x     = (const float*)d_in[0];
    const float* W_ih1 = (const float*)d_in[1];
    const float* W_hh1 = (const float*)d_in[2];
    const float* b_ih1 = (const float*)d_in[3];
    const float* b_hh1 = (const float*)d_in[4];
    const float* W_ih2 = (const float*)d_in[5];
    const float* W_hh2 = (const float*)d_in[6];
    const float* b_ih2 = (const float*)d_in[7];
    const float* b_hh2 = (const float*)d_in[8];
    const float* W_fc  = (const float*)d_in[9];
    const float* b_fc  = (const float*)d_in[10];
    float* out = (float*)d_out;

    fused_kernel<<<NPAIR, 32>>>(x, W_ih1, W_hh1, b_ih1, b_hh1,
                                W_ih2, W_hh2, b_ih2, b_hh2, W_fc, b_fc, out);
}

// round 5
// speedup vs baseline: 1.1348x; 1.1348x over previous
#include <cuda_runtime.h>
#include <cstdint>

#define T_STEPS 1000
#define BATCH   2048
#define FEAT    40
#define H1      8
#define H2      6
#define G2      24

#define CT      10                    // timesteps per staged x-chunk
#define NCHUNK  (T_STEPS / CT)        // 100
#define F4ROW   (FEAT / 4)            // 10 float4 per t
#define SITES   (CT * F4ROW)          // 100 float4 sites per chunk
#define NITER   ((SITES + 31) / 32)   // 4

typedef unsigned long long u64;

// ---------------- f32x2 helpers ----------------
__device__ __forceinline__ u64 pack2(float x, float y) {
    u64 r; asm("mov.b64 %0, {%1, %2};" : "=l"(r) : "f"(x), "f"(y)); return r;
}
__device__ __forceinline__ void unpack2(u64 v, float& x, float& y) {
    asm("mov.b64 {%0, %1}, %2;" : "=f"(x), "=f"(y) : "l"(v));
}
__device__ __forceinline__ u64 fma2(u64 a, u64 b, u64 c) {
    u64 d; asm("fma.rn.f32x2 %0, %1, %2, %3;" : "=l"(d) : "l"(a), "l"(b), "l"(c)); return d;
}
__device__ __forceinline__ u64 mul2(u64 a, u64 b) {
    u64 d; asm("mul.rn.f32x2 %0, %1, %2;" : "=l"(d) : "l"(a), "l"(b)); return d;
}
__device__ __forceinline__ u64 add2(u64 a, u64 b) {
    u64 d; asm("add.rn.f32x2 %0, %1, %2;" : "=l"(d) : "l"(a), "l"(b)); return d;
}
__device__ __forceinline__ u64 scale2(u64 v, float s) {
    float a, b; unpack2(v, a, b); return pack2(a * s, b * s);
}
__device__ __forceinline__ float hadd2(u64 v) {
    float a, b; unpack2(v, a, b); return a + b;
}

// ---------------- activations: 1 MUFU; input scale folded into weights ----
__device__ __forceinline__ float tanha(float x) {
    float r; asm("tanh.approx.f32 %0, %1;" : "=f"(r) : "f"(x)); return r;
}
__device__ __forceinline__ float shflf(float v, int src) {
    return __shfl_sync(0xffffffffu, v, src & 31);
}

// ============================================================================
// one fused LSTM step: layer1(i) + layer2(i-1), single batch element.
// slab (float[24]): [0..7]=h1, [8..15]=x2, [16..21]=h2
// ============================================================================
template <int RD>
__device__ __forceinline__ void lstm_step(
    float en, int tc, int lane,
    const float* __restrict__ xr,
    float (*shs)[24],
    const u64* __restrict__ w2,           // 20 feature-pair weights (cm-scaled)
    const u64* __restrict__ w1p,          // 4  h1-pair weights
    const u64* __restrict__ wi2p,         // 4  x2-pair weights
    const u64* __restrict__ wh2p,         // 3  h2-pair weights
    u64 bias1p, u64 bias2p,
    float cn1, float ca1, float cn2, float ca2,
    float& c1, float& c2)
{
    constexpr int WR = RD ^ 1;

    // ---- x projection: 20 fma2 over feature pairs (broadcast LDS) ----
    const ulonglong2* q = reinterpret_cast<const ulonglong2*>(xr + tc * FEAT);
    ulonglong2 v = q[0];
    u64 A = fma2(w2[0], v.x, bias1p);
    u64 B = mul2(w2[1], v.y);
#pragma unroll
    for (int p = 1; p < F4ROW; p++) {
        v = q[p];
        A = fma2(w2[2 * p],     v.x, A);
        B = fma2(w2[2 * p + 1], v.y, B);
    }

    // ---- hidden loads (broadcast) ----
    const ulonglong2* hp = reinterpret_cast<const ulonglong2*>(&shs[RD][0]);
    ulonglong2 h01 = hp[0];   // h1[0..3]
    ulonglong2 h23 = hp[1];   // h1[4..7]
    ulonglong2 x01 = hp[2];   // x2[0..3]
    ulonglong2 x23 = hp[3];   // x2[4..7]
    ulonglong2 h2a = hp[4];   // h2[0..3]
    u64        h2b = reinterpret_cast<const u64*>(&shs[RD][0])[10]; // h2[4..5]

    // ---- layer1 hidden MAC ----
    u64 C = mul2(h01.x, w1p[0]);
    C = fma2(h01.y, w1p[1], C);
    C = fma2(h23.x, w1p[2], C);
    C = fma2(h23.y, w1p[3], C);
    float g1 = hadd2(add2(add2(A, B), C));

    // ---- layer2 MAC ----
    u64 P = fma2(x01.x, wi2p[0], bias2p);
    u64 Q = mul2(x01.y, wi2p[1]);
    P = fma2(x23.x, wi2p[2], P);
    Q = fma2(x23.y, wi2p[3], Q);
    P = fma2(h2a.x, wh2p[0], P);
    Q = fma2(h2a.y, wh2p[1], Q);
    P = fma2(h2b,   wh2p[2], P);
    float g2 = hadd2(add2(P, Q));

    // ---- activations ----
    float a1 = fmaf(cn1, tanha(g1), ca1);
    float a2 = fmaf(cn2, tanha(g2), ca2);

    // ---- gate gathers ----
    float f1 = shflf(a1, lane + 8);
    float i1 = shflf(a1, lane + 16);
    float o1 = shflf(a1, lane + 24);
    float f2 = shflf(a2, lane + 6);
    float i2 = shflf(a2, lane + 12);
    float o2 = shflf(a2, lane + 18);

    // ---- layer1 state (lanes 0..7) ----
    c1 = fmaf(f1, c1, a1 * i1);
    float h1v = o1 * tanha(c1);
    float x2v = tanha(h1v);

    // ---- layer2 state (lanes 0..5) ----
    c2 = en * fmaf(f2, c2, a2 * i2);
    float h2v = o2 * tanha(c2);

    if (lane < H1) {
        shs[WR][lane]     = h1v;
        shs[WR][8 + lane] = x2v;
    }
    if (lane < H2) shs[WR][16 + lane] = h2v;
    __syncwarp();
}

// ============================================================================
// fused kernel: 1 warp per batch element (2048 warps)
// ============================================================================
__global__ void __launch_bounds__(32)
fused_kernel(const float* __restrict__ x,
             const float* __restrict__ W_ih1,
             const float* __restrict__ W_hh1,
             const float* __restrict__ b_ih1,
             const float* __restrict__ b_hh1,
             const float* __restrict__ W_ih2,
             const float* __restrict__ W_hh2,
             const float* __restrict__ b_ih2,
             const float* __restrict__ b_hh2,
             const float* __restrict__ W_fc,
             const float* __restrict__ b_fc,
             float* __restrict__ out) {
    __shared__ __align__(16) float shs[2][24];
    __shared__ __align__(16) float sx[2][CT][FEAT];

    int lane = threadIdx.x;
    int b    = blockIdx.x;

    // activation constants; cm (input scale) folded into weights
    bool t1 = ((lane >> 3) == 2);
    float cm1 = t1 ? 1.f : 0.5f, cn1 = t1 ? 1.f : 0.5f, ca1 = t1 ? 0.f : 0.5f;
    bool t2 = (lane >= 12 && lane < 18);
    float cm2 = t2 ? 1.f : 0.5f, cn2 = t2 ? 1.f : 0.5f, ca2 = t2 ? 0.f : 0.5f;

    // ---- per-lane weights (pair-packed along input dim, cm-scaled) ----
    u64 w2[FEAT / 2];
    {
        const u64* wrow = reinterpret_cast<const u64*>(W_ih1 + lane * FEAT);
#pragma unroll
        for (int p = 0; p < FEAT / 2; p++) w2[p] = scale2(wrow[p], cm1);
    }
    u64 w1p[H1 / 2];
#pragma unroll
    for (int j = 0; j < H1 / 2; j++)
        w1p[j] = pack2(cm1 * W_hh1[lane * H1 + 2 * j], cm1 * W_hh1[lane * H1 + 2 * j + 1]);

    u64 wi2p[H1 / 2], wh2p[H2 / 2], bias2p = 0ull;
#pragma unroll
    for (int j = 0; j < H1 / 2; j++) wi2p[j] = 0ull;
#pragma unroll
    for (int j = 0; j < H2 / 2; j++) wh2p[j] = 0ull;
    if (lane < G2) {
#pragma unroll
        for (int j = 0; j < H1 / 2; j++)
            wi2p[j] = pack2(cm2 * W_ih2[lane * H1 + 2 * j], cm2 * W_ih2[lane * H1 + 2 * j + 1]);
#pragma unroll
        for (int j = 0; j < H2 / 2; j++)
            wh2p[j] = pack2(cm2 * W_hh2[lane * H2 + 2 * j], cm2 * W_hh2[lane * H2 + 2 * j + 1]);
        bias2p = pack2(cm2 * (b_ih2[lane] + b_hh2[lane]), 0.f);
    }
    u64 bias1p = pack2(cm1 * (b_ih1[lane] + b_hh1[lane]), 0.f);

    if (lane < 24) shs[1][lane] = 0.f;    // zero state read by step 0

    // ---- x chunk staging ----
    const float4* xb = reinterpret_cast<const float4*>(x + (size_t)b * T_STEPS * FEAT);

    {   // preload chunk 0 into buffer 0
        float4 f4[NITER];
#pragma unroll
        for (int i = 0; i < NITER; i++) {
            int s = lane + 32 * i;
            if (s < SITES) f4[i] = xb[s];
        }
        float4* sb = reinterpret_cast<float4*>(&sx[0][0][0]);
#pragma unroll
        for (int i = 0; i < NITER; i++) {
            int s = lane + 32 * i;
            if (s < SITES) sb[s] = f4[i];
        }
    }
    __syncwarp();

    float c1 = 0.f, c2 = 0.f;

#pragma unroll 1
    for (int c = 0; c < NCHUNK; c++) {
        int bb = c & 1;
        const float* xr = &sx[bb][0][0];

        // prefetch chunk c+1 (clamped)
        int cn = (c + 1 < NCHUNK) ? c + 1 : c;
        const float4* p0 = xb + cn * SITES;
        float4 f4[NITER];
#pragma unroll
        for (int i = 0; i < NITER; i++) {
            int s = lane + 32 * i;
            if (s < SITES) f4[i] = p0[s];
        }

        float en0 = (c == 0) ? 0.f : 1.f;
        lstm_step<1>(en0, 0, lane, xr, shs, w2, w1p, wi2p, wh2p, bias1p, bias2p,
                     cn1, ca1, cn2, ca2, c1, c2);
        lstm_step<0>(1.f, 1, lane, xr, shs, w2, w1p, wi2p, wh2p, bias1p, bias2p,
                     cn1, ca1, cn2, ca2, c1, c2);
        lstm_step<1>(1.f, 2, lane, xr, shs, w2, w1p, wi2p, wh2p, bias1p, bias2p,
                     cn1, ca1, cn2, ca2, c1, c2);
        lstm_step<0>(1.f, 3, lane, xr, shs, w2, w1p, wi2p, wh2p, bias1p, bias2p,
                     cn1, ca1, cn2, ca2, c1, c2);

        {   // stash prefetched chunk into the other buffer
            float4* sb = reinterpret_cast<float4*>(&sx[bb ^ 1][0][0]);
#pragma unroll
            for (int i = 0; i < NITER; i++) {
                int s = lane + 32 * i;
                if (s < SITES) sb[s] = f4[i];
            }
        }

#pragma unroll 3
        for (int k = 2; k < 5; k++) {
            lstm_step<1>(1.f, 2 * k,     lane, xr, shs, w2, w1p, wi2p, wh2p, bias1p, bias2p,
                         cn1, ca1, cn2, ca2, c1, c2);
            lstm_step<0>(1.f, 2 * k + 1, lane, xr, shs, w2, w1p, wi2p, wh2p, bias1p, bias2p,
                         cn1, ca1, cn2, ca2, c1, c2);
        }
    }

    // ---- epilogue: layer2(999) from slab[1]: x2(999), h2(998) ----
    {
        const ulonglong2* hp = reinterpret_cast<const ulonglong2*>(&shs[1][0]);
        ulonglong2 x01 = hp[2];
        ulonglong2 x23 = hp[3];
        ulonglong2 h2a = hp[4];
        u64        h2b = reinterpret_cast<const u64*>(&shs[1][0])[10];

        u64 P = fma2(x01.x, wi2p[0], bias2p);
        u64 Q = mul2(x01.y, wi2p[1]);
        P = fma2(x23.x, wi2p[2], P);
        Q = fma2(x23.y, wi2p[3], Q);
        P = fma2(h2a.x, wh2p[0], P);
        Q = fma2(h2a.y, wh2p[1], Q);
        P = fma2(h2b,   wh2p[2], P);
        float g2 = hadd2(add2(P, Q));

        float a2 = fmaf(cn2, tanha(g2), ca2);
        float f2 = shflf(a2, lane + 6);
        float i2 = shflf(a2, lane + 12);
        float o2 = shflf(a2, lane + 18);
        c2 = fmaf(f2, c2, a2 * i2);
        float tx = tanha(o2 * tanha(c2));   // tanh(h2(999)), valid lanes 0..5

        // FC + sigmoid
        float s = b_fc[0];
#pragma unroll
        for (int j = 0; j < H2; j++)
            s = fmaf(shflf(tx, j), W_fc[j], s);
        if (lane == 0)
            out[b] = fmaf(0.5f, tanha(0.5f * s), 0.5f);
    }
}

// ============================================================================
extern "C" void kernel_launch(void* const* d_in, const int* in_sizes, int n_in,
                              void* d_out, int out_size) {
    const float* x     = (const float*)d_in[0];
    const float* W_ih1 = (const float*)d_in[1];
    const float* W_hh1 = (const float*)d_in[2];
    const float* b_ih1 = (const float*)d_in[3];
    const float* b_hh1 = (const float*)d_in[4];
    const float* W_ih2 = (const float*)d_in[5];
    const float* W_hh2 = (const float*)d_in[6];
    const float* b_ih2 = (const float*)d_in[7];
    const float* b_hh2 = (const float*)d_in[8];
    const float* W_fc  = (const float*)d_in[9];
    const float* b_fc  = (const float*)d_in[10];
    float* out = (float*)d_out;

    fused_kernel<<<BATCH, 32>>>(x, W_ih1, W_hh1, b_ih1, b_hh1,
                                W_ih2, W_hh2, b_ih2, b_hh2, W_fc, b_fc, out);
}